// round 7
// baseline (speedup 1.0000x reference)
#include <cuda_runtime.h>
#include <cuda_bf16.h>

#define COLS  4096
#define TPB   512
#define RPC   4            // rows per CTA (11008 % 4 == 0)
#define EPR   8            // elements per thread per row (2 x float4)
#define NWARP (TPB / 32)

__device__ __forceinline__ float fsign(float x) {
    return (x > 0.f) ? 1.f : ((x < 0.f) ? -1.f : 0.f);
}

// N-value block reduction in ONE barrier round. s = N dedicated smem rows.
template <int N>
__device__ __forceinline__ void block_reduceN(float* a, float (*s)[NWARP]) {
    #pragma unroll
    for (int o = 16; o; o >>= 1) {
        #pragma unroll
        for (int i = 0; i < N; i++)
            a[i] += __shfl_xor_sync(0xffffffffu, a[i], o);
    }
    const int w = threadIdx.x >> 5;
    if ((threadIdx.x & 31) == 0) {
        #pragma unroll
        for (int i = 0; i < N; i++) s[i][w] = a[i];
    }
    __syncthreads();
    if (threadIdx.x < 32) {
        const bool in = threadIdx.x < NWARP;
        #pragma unroll
        for (int i = 0; i < N; i++) a[i] = in ? s[i][threadIdx.x] : 0.f;
        #pragma unroll
        for (int o = NWARP / 2; o; o >>= 1) {
            #pragma unroll
            for (int i = 0; i < N; i++)
                a[i] += __shfl_xor_sync(0xffffffffu, a[i], o);
        }
        if (threadIdx.x == 0) {
            #pragma unroll
            for (int i = 0; i < N; i++) s[i][0] = a[i];
        }
    }
    __syncthreads();
    #pragma unroll
    for (int i = 0; i < N; i++) a[i] = s[i][0];
}

__global__ __launch_bounds__(TPB, 2) void braq_4row_kernel(
    const float* __restrict__ x,
    const int* __restrict__ mask,
    float* __restrict__ out)
{
    __shared__ float sbuf[20][NWARP];   // sites: [0..7], [8..15], [16..19]
    const int tid = threadIdx.x;
    const size_t base = (size_t)blockIdx.x * RPC * COLS;

    float    v[RPC][EPR];   // masked x (0 outside mask)
    unsigned mb = 0;        // packed mask bits: row r, elem k -> bit (r*8+k)

    // ---- load all 4 rows (16 x LDG.128/thread) + round-1 partials ----
    float red[8];           // [sum0..3, cnt0..3]
    #pragma unroll
    for (int i = 0; i < 8; i++) red[i] = 0.f;
    #pragma unroll
    for (int r = 0; r < RPC; r++) {
        const float4* x4 = reinterpret_cast<const float4*>(x + base + (size_t)r * COLS);
        const int4*   m4 = reinterpret_cast<const int4*>(mask + base + (size_t)r * COLS);
        float4 xa = __ldcs(&x4[tid]);
        float4 xb = __ldcs(&x4[tid + TPB]);
        int4   ma = __ldcs(&m4[tid]);
        int4   mbv = __ldcs(&m4[tid + TPB]);
        const float xs[8] = {xa.x, xa.y, xa.z, xa.w, xb.x, xb.y, xb.z, xb.w};
        const int   ms[8] = {ma.x, ma.y, ma.z, ma.w, mbv.x, mbv.y, mbv.z, mbv.w};
        #pragma unroll
        for (int k = 0; k < EPR; k++) {
            const bool m = (ms[k] != 0);
            const float val = m ? xs[k] : 0.f;
            v[r][k] = val;
            mb |= (m ? 1u : 0u) << (r * 8 + k);
            red[r]     += val;
            red[4 + r] += m ? 1.f : 0.f;
        }
    }

    block_reduceN<8>(red, &sbuf[0]);
    float inv[RPC], mean1[RPC];
    #pragma unroll
    for (int r = 0; r < RPC; r++) {
        inv[r]   = (red[4 + r] > 0.f) ? (1.f / red[4 + r]) : 0.f;  // empty-row safe
        mean1[r] = red[r] * inv[r];
    }

    // ---- round 2: sum|d| and sum sign(d), all rows in one barrier round ----
    float red2[8];          // [abs0..3, sgn0..3]
    #pragma unroll
    for (int i = 0; i < 8; i++) red2[i] = 0.f;
    #pragma unroll
    for (int r = 0; r < RPC; r++) {
        #pragma unroll
        for (int k = 0; k < EPR; k++) {
            const bool m = (mb >> (r * 8 + k)) & 1u;
            const float dm = m ? (v[r][k] - mean1[r]) : 0.f;  // one SEL covers abs+sign
            red2[r]     += fabsf(dm);
            red2[4 + r] += fsign(dm);
        }
    }
    block_reduceN<8>(red2, &sbuf[8]);
    float scale1[RPC], mean2[RPC];
    #pragma unroll
    for (int r = 0; r < RPC; r++) {
        scale1[r] = red2[r] * inv[r];
        // mean2 = ((S - mean1*cnt) - scale1 * sum_sign) / cnt  (analytic)
        mean2[r]  = (red[r] - mean1[r] * red[4 + r] - scale1[r] * red2[4 + r]) * inv[r];
    }

    // ---- round 3: sum|r2 - mean2| (recompute b1/r2) ----
    float a2[RPC] = {0.f, 0.f, 0.f, 0.f};
    #pragma unroll
    for (int r = 0; r < RPC; r++) {
        #pragma unroll
        for (int k = 0; k < EPR; k++) {
            const bool m  = (mb >> (r * 8 + k)) & 1u;
            const float b1 = fsign(v[r][k] - mean1[r]) * scale1[r] + mean1[r];
            const float cm = m ? ((v[r][k] - b1) - mean2[r]) : 0.f;
            a2[r] += fabsf(cm);
        }
    }
    block_reduceN<4>(a2, &sbuf[16]);

    // ---- stores: 8 x STG.128 ----
    #pragma unroll
    for (int r = 0; r < RPC; r++) {
        const float scale2 = a2[r] * inv[r];
        float4* o4 = reinterpret_cast<float4*>(out + base + (size_t)r * COLS);
        #pragma unroll
        for (int i = 0; i < 2; i++) {
            float t[4];
            #pragma unroll
            for (int j = 0; j < 4; j++) {
                const int k = i * 4 + j;
                const bool m  = (mb >> (r * 8 + k)) & 1u;
                const float b1 = fsign(v[r][k] - mean1[r]) * scale1[r] + mean1[r];
                const float c2 = (v[r][k] - b1) - mean2[r];
                t[j] = m ? (b1 + fsign(c2) * scale2 + mean2[r]) : 0.f;
            }
            float4 ov; ov.x = t[0]; ov.y = t[1]; ov.z = t[2]; ov.w = t[3];
            __stcs(&o4[tid + i * TPB], ov);
        }
    }
}

extern "C" void kernel_launch(void* const* d_in, const int* in_sizes, int n_in,
                              void* d_out, int out_size) {
    const float* x    = (const float*)d_in[0];
    const int*   mask = (const int*)d_in[1];
    float*       out  = (float*)d_out;
    const int rows = in_sizes[0] / COLS;   // 11008 (divisible by RPC=4)
    braq_4row_kernel<<<rows / RPC, TPB>>>(x, mask, out);
}

// round 8
// speedup vs baseline: 1.7942x; 1.7942x over previous
#include <cuda_runtime.h>
#include <cuda_bf16.h>

#define COLS  4096
#define TPB   256
#define EPT   16           // 4 x float4 per thread
#define NWARP (TPB / 32)   // 8

__device__ __forceinline__ float fsign(float x) {
    return (x > 0.f) ? 1.f : ((x < 0.f) ? -1.f : 0.f);
}

// Pair reduction, one barrier round, dedicated smem rows per call site.
__device__ __forceinline__ float2 block_reduce2(float a, float b, float (*s)[NWARP]) {
    #pragma unroll
    for (int o = 16; o; o >>= 1) {
        a += __shfl_xor_sync(0xffffffffu, a, o);
        b += __shfl_xor_sync(0xffffffffu, b, o);
    }
    const int w = threadIdx.x >> 5;
    if ((threadIdx.x & 31) == 0) { s[0][w] = a; s[1][w] = b; }
    __syncthreads();
    if (threadIdx.x < 32) {
        const bool in = threadIdx.x < NWARP;
        a = in ? s[0][threadIdx.x] : 0.f;
        b = in ? s[1][threadIdx.x] : 0.f;
        #pragma unroll
        for (int o = NWARP / 2; o; o >>= 1) {
            a += __shfl_xor_sync(0xffffffffu, a, o);
            b += __shfl_xor_sync(0xffffffffu, b, o);
        }
        if (threadIdx.x == 0) { s[0][0] = a; s[1][0] = b; }
    }
    __syncthreads();
    return make_float2(s[0][0], s[1][0]);
}

__device__ __forceinline__ float block_reduce1(float a, float* sw) {
    #pragma unroll
    for (int o = 16; o; o >>= 1) a += __shfl_xor_sync(0xffffffffu, a, o);
    if ((threadIdx.x & 31) == 0) sw[threadIdx.x >> 5] = a;
    __syncthreads();
    if (threadIdx.x < 32) {
        a = (threadIdx.x < NWARP) ? sw[threadIdx.x] : 0.f;
        #pragma unroll
        for (int o = NWARP / 2; o; o >>= 1) a += __shfl_xor_sync(0xffffffffu, a, o);
        if (threadIdx.x == 0) sw[0] = a;
    }
    __syncthreads();
    return sw[0];
}

__global__ __launch_bounds__(TPB, 5) void braq_fine_kernel(
    const float* __restrict__ x,
    const int* __restrict__ mask,
    float* __restrict__ out)
{
    __shared__ float sbuf[5][NWARP];
    const int tid = threadIdx.x;
    const size_t base = (size_t)blockIdx.x * COLS;
    const float4* __restrict__ x4 = reinterpret_cast<const float4*>(x + base);
    const int4*   __restrict__ m4 = reinterpret_cast<const int4*>(mask + base);

    // ---- front-batched load burst: 8 x LDG.128 (max MLP) ----
    float4 xv0 = __ldcs(&x4[tid]);
    float4 xv1 = __ldcs(&x4[tid + TPB]);
    float4 xv2 = __ldcs(&x4[tid + 2 * TPB]);
    float4 xv3 = __ldcs(&x4[tid + 3 * TPB]);
    int4   mv0 = __ldcs(&m4[tid]);
    int4   mv1 = __ldcs(&m4[tid + TPB]);
    int4   mv2 = __ldcs(&m4[tid + 2 * TPB]);
    int4   mv3 = __ldcs(&m4[tid + 3 * TPB]);

    float    v[EPT];   // masked x (0 outside mask)
    unsigned mb = 0;   // 16 mask bits
    float s = 0.f, c = 0.f;
    {
        const float xs[EPT] = {xv0.x, xv0.y, xv0.z, xv0.w,  xv1.x, xv1.y, xv1.z, xv1.w,
                               xv2.x, xv2.y, xv2.z, xv2.w,  xv3.x, xv3.y, xv3.z, xv3.w};
        const int   ms[EPT] = {mv0.x, mv0.y, mv0.z, mv0.w,  mv1.x, mv1.y, mv1.z, mv1.w,
                               mv2.x, mv2.y, mv2.z, mv2.w,  mv3.x, mv3.y, mv3.z, mv3.w};
        #pragma unroll
        for (int k = 0; k < EPT; k++) {
            const bool m = (ms[k] != 0);
            const float val = m ? xs[k] : 0.f;
            v[k] = val;
            mb |= (m ? 1u : 0u) << k;
            s += val;
            c += m ? 1.f : 0.f;
        }
    }

    // ---- round 1: (sum, count) ----
    float2 r1 = block_reduce2(s, c, &sbuf[0]);
    const float inv   = (r1.y > 0.f) ? (1.f / r1.y) : 0.f;   // empty-row safe
    const float mean1 = r1.x * inv;

    // ---- round 2: (sum|d|, sum sign(d)), d = masked(v - mean1) ----
    float sAbs = 0.f, sSgn = 0.f;
    #pragma unroll
    for (int k = 0; k < EPT; k++) {
        const bool m = (mb >> k) & 1u;
        const float dm = m ? (v[k] - mean1) : 0.f;  // one SEL covers abs+sign
        sAbs += fabsf(dm);
        sSgn += fsign(dm);
    }
    float2 rr = block_reduce2(sAbs, sSgn, &sbuf[2]);
    const float scale1 = rr.x * inv;
    // mean2 = ((S - mean1*cnt) - scale1 * sum_sign) / cnt   (analytic)
    const float mean2  = (r1.x - mean1 * r1.y - scale1 * rr.y) * inv;

    // ---- round 3: sum|r2 - mean2| (recompute b1/r2) ----
    float a2 = 0.f;
    #pragma unroll
    for (int k = 0; k < EPT; k++) {
        const bool m  = (mb >> k) & 1u;
        const float b1 = fsign(v[k] - mean1) * scale1 + mean1;
        const float cm = m ? ((v[k] - b1) - mean2) : 0.f;
        a2 += fabsf(cm);
    }
    const float scale2 = block_reduce1(a2, sbuf[4]) * inv;

    // ---- store: 4 x STG.128 (recompute per element) ----
    float4* __restrict__ o4 = reinterpret_cast<float4*>(out + base);
    #pragma unroll
    for (int i = 0; i < 4; i++) {
        float t[4];
        #pragma unroll
        for (int j = 0; j < 4; j++) {
            const int k = i * 4 + j;
            const bool m  = (mb >> k) & 1u;
            const float b1 = fsign(v[k] - mean1) * scale1 + mean1;
            const float c2 = (v[k] - b1) - mean2;
            t[j] = m ? (b1 + fsign(c2) * scale2 + mean2) : 0.f;
        }
        float4 ov; ov.x = t[0]; ov.y = t[1]; ov.z = t[2]; ov.w = t[3];
        __stcs(&o4[tid + i * TPB], ov);
    }
}

extern "C" void kernel_launch(void* const* d_in, const int* in_sizes, int n_in,
                              void* d_out, int out_size) {
    const float* x    = (const float*)d_in[0];
    const int*   mask = (const int*)d_in[1];
    float*       out  = (float*)d_out;
    const int rows = in_sizes[0] / COLS;   // 11008
    braq_fine_kernel<<<rows, TPB>>>(x, mask, out);
}

// round 9
// speedup vs baseline: 1.8823x; 1.0491x over previous
#include <cuda_runtime.h>
#include <cuda_bf16.h>

#define COLS   4096
#define COLS_F 4096.0f
#define TPB    256
#define EPT    16           // 4 x float4 per thread
#define NWARP  (TPB / 32)   // 8

__device__ __forceinline__ float fsign(float x) {
    return (x > 0.f) ? 1.f : ((x < 0.f) ? -1.f : 0.f);
}

// Pair reduction, one barrier round, dedicated smem rows per call site.
__device__ __forceinline__ float2 block_reduce2(float a, float b, float (*s)[NWARP]) {
    #pragma unroll
    for (int o = 16; o; o >>= 1) {
        a += __shfl_xor_sync(0xffffffffu, a, o);
        b += __shfl_xor_sync(0xffffffffu, b, o);
    }
    const int w = threadIdx.x >> 5;
    if ((threadIdx.x & 31) == 0) { s[0][w] = a; s[1][w] = b; }
    __syncthreads();
    if (threadIdx.x < 32) {
        const bool in = threadIdx.x < NWARP;
        a = in ? s[0][threadIdx.x] : 0.f;
        b = in ? s[1][threadIdx.x] : 0.f;
        #pragma unroll
        for (int o = NWARP / 2; o; o >>= 1) {
            a += __shfl_xor_sync(0xffffffffu, a, o);
            b += __shfl_xor_sync(0xffffffffu, b, o);
        }
        if (threadIdx.x == 0) { s[0][0] = a; s[1][0] = b; }
    }
    __syncthreads();
    return make_float2(s[0][0], s[1][0]);
}

__device__ __forceinline__ float block_reduce1(float a, float* sw) {
    #pragma unroll
    for (int o = 16; o; o >>= 1) a += __shfl_xor_sync(0xffffffffu, a, o);
    if ((threadIdx.x & 31) == 0) sw[threadIdx.x >> 5] = a;
    __syncthreads();
    if (threadIdx.x < 32) {
        a = (threadIdx.x < NWARP) ? sw[threadIdx.x] : 0.f;
        #pragma unroll
        for (int o = NWARP / 2; o; o >>= 1) a += __shfl_xor_sync(0xffffffffu, a, o);
        if (threadIdx.x == 0) sw[0] = a;
    }
    __syncthreads();
    return sw[0];
}

__global__ __launch_bounds__(TPB, 5) void braq_nomask_kernel(
    const float* __restrict__ x,
    const int* __restrict__ mask,
    float* __restrict__ out)
{
    __shared__ float sbuf[5][NWARP];
    const int tid = threadIdx.x;
    const size_t base = (size_t)blockIdx.x * COLS;
    const float4* __restrict__ x4 = reinterpret_cast<const float4*>(x + base);
    const int4*   __restrict__ m4 = reinterpret_cast<const int4*>(mask + base);

    // ---- front-batched load burst: 8 x LDG.128 ----
    float4 xv0 = __ldcs(&x4[tid]);
    float4 xv1 = __ldcs(&x4[tid + TPB]);
    float4 xv2 = __ldcs(&x4[tid + 2 * TPB]);
    float4 xv3 = __ldcs(&x4[tid + 3 * TPB]);
    int4   mv0 = __ldcs(&m4[tid]);
    int4   mv1 = __ldcs(&m4[tid + TPB]);
    int4   mv2 = __ldcs(&m4[tid + 2 * TPB]);
    int4   mv3 = __ldcs(&m4[tid + 3 * TPB]);

    float    v[EPT];   // masked x (exactly 0 outside mask)
    unsigned mb = 0;   // 16 mask bits (used only in the store pass)
    float s = 0.f, c = 0.f;
    {
        const float xs[EPT] = {xv0.x, xv0.y, xv0.z, xv0.w,  xv1.x, xv1.y, xv1.z, xv1.w,
                               xv2.x, xv2.y, xv2.z, xv2.w,  xv3.x, xv3.y, xv3.z, xv3.w};
        const int   ms[EPT] = {mv0.x, mv0.y, mv0.z, mv0.w,  mv1.x, mv1.y, mv1.z, mv1.w,
                               mv2.x, mv2.y, mv2.z, mv2.w,  mv3.x, mv3.y, mv3.z, mv3.w};
        #pragma unroll
        for (int k = 0; k < EPT; k++) {
            const bool m = (ms[k] != 0);
            const float val = m ? xs[k] : 0.f;
            v[k] = val;
            mb |= (m ? 1u : 0u) << k;
            s += val;
            c += m ? 1.f : 0.f;
        }
    }

    // ---- round 1: (sum, count) ----
    float2 r1 = block_reduce2(s, c, &sbuf[0]);
    const float cnt   = r1.y;
    const float inv   = (cnt > 0.f) ? (1.f / cnt) : 0.f;   // empty-row safe
    const float mean1 = r1.x * inv;
    const float n_unm = COLS_F - cnt;                      // exact small integer

    // ---- round 2 (UNMASKED over all elems): sum|d|, sum sign(d) ----
    // unmasked element: v=0 -> d = -mean1 (row constant) -> correct after reduce
    float sAbs = 0.f, sSgn = 0.f;
    #pragma unroll
    for (int k = 0; k < EPT; k++) {
        const float d = v[k] - mean1;
        sAbs += fabsf(d);
        sSgn += fsign(d);
    }
    float2 rr = block_reduce2(sAbs, sSgn, &sbuf[2]);
    const float A = rr.x - n_unm * fabsf(mean1);           // masked sum |d|
    const float G = rr.y + n_unm * fsign(mean1);           // masked sum sign(d)
    const float scale1 = A * inv;
    // mean2 = ((S - mean1*cnt) - scale1 * G) / cnt  (analytic)
    const float mean2  = (r1.x - mean1 * cnt - scale1 * G) * inv;

    // ---- round 3 (UNMASKED): sum|c2|, c2 = d - sign(d)*scale1 - mean2 ----
    float a2 = 0.f;
    #pragma unroll
    for (int k = 0; k < EPT; k++) {
        const float d  = v[k] - mean1;
        const float c2 = d - fsign(d) * scale1 - mean2;
        a2 += fabsf(c2);
    }
    // unmasked constant: d0 = -mean1
    const float c0 = (-mean1) - fsign(-mean1) * scale1 - mean2;
    const float a2m = block_reduce1(a2, sbuf[4]) - n_unm * fabsf(c0);
    const float scale2 = a2m * inv;

    // ---- store: masked (b1 + sign(c2)*scale2 + mean2) ----
    float4* __restrict__ o4 = reinterpret_cast<float4*>(out + base);
    #pragma unroll
    for (int i = 0; i < 4; i++) {
        float t[4];
        #pragma unroll
        for (int j = 0; j < 4; j++) {
            const int k = i * 4 + j;
            const bool m = (mb >> k) & 1u;
            const float d   = v[k] - mean1;
            const float sg  = fsign(d);
            const float b1  = sg * scale1 + mean1;
            const float c2  = d - sg * scale1 - mean2;
            t[j] = m ? (b1 + fsign(c2) * scale2 + mean2) : 0.f;
        }
        float4 ov; ov.x = t[0]; ov.y = t[1]; ov.z = t[2]; ov.w = t[3];
        __stcs(&o4[tid + i * TPB], ov);
    }
}

extern "C" void kernel_launch(void* const* d_in, const int* in_sizes, int n_in,
                              void* d_out, int out_size) {
    const float* x    = (const float*)d_in[0];
    const int*   mask = (const int*)d_in[1];
    float*       out  = (float*)d_out;
    const int rows = in_sizes[0] / COLS;   // 11008
    braq_nomask_kernel<<<rows, TPB>>>(x, mask, out);
}

// round 10
// speedup vs baseline: 1.9407x; 1.0310x over previous
#include <cuda_runtime.h>
#include <cuda_bf16.h>

#define COLS   4096
#define COLS_F 4096.0f
#define TPB    256
#define EPT    16           // 4 x float4 per thread
#define NWARP  (TPB / 32)   // 8

// Pair reduction, one barrier round, dedicated smem rows per call site.
__device__ __forceinline__ float2 block_reduce2(float a, float b, float (*s)[NWARP]) {
    #pragma unroll
    for (int o = 16; o; o >>= 1) {
        a += __shfl_xor_sync(0xffffffffu, a, o);
        b += __shfl_xor_sync(0xffffffffu, b, o);
    }
    const int w = threadIdx.x >> 5;
    if ((threadIdx.x & 31) == 0) { s[0][w] = a; s[1][w] = b; }
    __syncthreads();
    if (threadIdx.x < 32) {
        const bool in = threadIdx.x < NWARP;
        a = in ? s[0][threadIdx.x] : 0.f;
        b = in ? s[1][threadIdx.x] : 0.f;
        #pragma unroll
        for (int o = NWARP / 2; o; o >>= 1) {
            a += __shfl_xor_sync(0xffffffffu, a, o);
            b += __shfl_xor_sync(0xffffffffu, b, o);
        }
        if (threadIdx.x == 0) { s[0][0] = a; s[1][0] = b; }
    }
    __syncthreads();
    return make_float2(s[0][0], s[1][0]);
}

__device__ __forceinline__ float block_reduce1(float a, float* sw) {
    #pragma unroll
    for (int o = 16; o; o >>= 1) a += __shfl_xor_sync(0xffffffffu, a, o);
    if ((threadIdx.x & 31) == 0) sw[threadIdx.x >> 5] = a;
    __syncthreads();
    if (threadIdx.x < 32) {
        a = (threadIdx.x < NWARP) ? sw[threadIdx.x] : 0.f;
        #pragma unroll
        for (int o = NWARP / 2; o; o >>= 1) a += __shfl_xor_sync(0xffffffffu, a, o);
        if (threadIdx.x == 0) sw[0] = a;
    }
    __syncthreads();
    return sw[0];
}

__global__ __launch_bounds__(TPB, 5) void braq_cs_kernel(
    const float* __restrict__ x,
    const int* __restrict__ mask,
    float* __restrict__ out)
{
    __shared__ float sbuf[5][NWARP];
    const int tid = threadIdx.x;
    const size_t base = (size_t)blockIdx.x * COLS;
    const float4* __restrict__ x4 = reinterpret_cast<const float4*>(x + base);
    const int4*   __restrict__ m4 = reinterpret_cast<const int4*>(mask + base);

    // ---- front-batched load burst: 8 x LDG.128 ----
    float4 xv0 = __ldcs(&x4[tid]);
    float4 xv1 = __ldcs(&x4[tid + TPB]);
    float4 xv2 = __ldcs(&x4[tid + 2 * TPB]);
    float4 xv3 = __ldcs(&x4[tid + 3 * TPB]);
    int4   mv0 = __ldcs(&m4[tid]);
    int4   mv1 = __ldcs(&m4[tid + TPB]);
    int4   mv2 = __ldcs(&m4[tid + 2 * TPB]);
    int4   mv3 = __ldcs(&m4[tid + 3 * TPB]);

    float    v[EPT];   // masked x (exactly 0 outside mask)
    unsigned mb = 0;   // 16 mask bits (used only in the store pass)
    float s = 0.f, c = 0.f;
    {
        const float xs[EPT] = {xv0.x, xv0.y, xv0.z, xv0.w,  xv1.x, xv1.y, xv1.z, xv1.w,
                               xv2.x, xv2.y, xv2.z, xv2.w,  xv3.x, xv3.y, xv3.z, xv3.w};
        const int   ms[EPT] = {mv0.x, mv0.y, mv0.z, mv0.w,  mv1.x, mv1.y, mv1.z, mv1.w,
                               mv2.x, mv2.y, mv2.z, mv2.w,  mv3.x, mv3.y, mv3.z, mv3.w};
        #pragma unroll
        for (int k = 0; k < EPT; k++) {
            const bool m = (ms[k] != 0);
            const float val = m ? xs[k] : 0.f;
            v[k] = val;
            mb |= (m ? 1u : 0u) << k;
            s += val;
            c += m ? 1.f : 0.f;
        }
    }

    // ---- round 1: (sum, count) ----
    float2 r1 = block_reduce2(s, c, &sbuf[0]);
    const float cnt   = r1.y;
    const float inv   = (cnt > 0.f) ? (1.f / cnt) : 0.f;   // empty-row safe
    const float mean1 = r1.x * inv;
    const float n_unm = COLS_F - cnt;                      // exact small integer
    const float d0    = 0.0f - mean1;                      // unmasked element's d (bit-exact)

    // ---- round 2 (UNMASKED over all elems): sum|d|, sum csign(1,d) ----
    float sAbs = 0.f, sSgn = 0.f;
    #pragma unroll
    for (int k = 0; k < EPT; k++) {
        const float d = v[k] - mean1;
        sAbs += fabsf(d);                 // |d| folds into FADD abs-modifier
        sSgn += copysignf(1.0f, d);       // 1 LOP3 (zero counted as ±1; measure-zero diff)
    }
    float2 rr = block_reduce2(sAbs, sSgn, &sbuf[2]);
    const float A = rr.x - n_unm * fabsf(d0);              // masked sum |d|
    const float G = rr.y - n_unm * copysignf(1.0f, d0);    // masked sum sign(d)
    const float scale1 = A * inv;
    // mean2 = ((S - mean1*cnt) - scale1 * G) / cnt  (analytic)
    const float mean2  = (r1.x - mean1 * cnt - scale1 * G) * inv;

    // ---- round 3 (UNMASKED): sum|c2|, c2 = d - csign(scale1,d) - mean2 ----
    float a2 = 0.f;
    #pragma unroll
    for (int k = 0; k < EPT; k++) {
        const float d  = v[k] - mean1;
        const float c2 = (d - copysignf(scale1, d)) - mean2;
        a2 += fabsf(c2);
    }
    const float c0 = (d0 - copysignf(scale1, d0)) - mean2;  // same expression shape
    const float a2m = block_reduce1(a2, sbuf[4]) - n_unm * fabsf(c0);
    const float scale2 = a2m * inv;

    // ---- store: masked ((mean1+mean2) + csign(scale1,d) + csign(scale2,c2)) ----
    const float M12 = mean1 + mean2;
    float4* __restrict__ o4 = reinterpret_cast<float4*>(out + base);
    #pragma unroll
    for (int i = 0; i < 4; i++) {
        float t[4];
        #pragma unroll
        for (int j = 0; j < 4; j++) {
            const int k = i * 4 + j;
            const bool m  = (mb >> k) & 1u;
            const float d  = v[k] - mean1;
            const float t1 = copysignf(scale1, d);
            const float c2 = (d - t1) - mean2;
            const float t2 = copysignf(scale2, c2);
            t[j] = m ? (M12 + t1 + t2) : 0.f;
        }
        float4 ov; ov.x = t[0]; ov.y = t[1]; ov.z = t[2]; ov.w = t[3];
        __stcs(&o4[tid + i * TPB], ov);
    }
}

extern "C" void kernel_launch(void* const* d_in, const int* in_sizes, int n_in,
                              void* d_out, int out_size) {
    const float* x    = (const float*)d_in[0];
    const int*   mask = (const int*)d_in[1];
    float*       out  = (float*)d_out;
    const int rows = in_sizes[0] / COLS;   // 11008
    braq_cs_kernel<<<rows, TPB>>>(x, mask, out);
}